// round 2
// baseline (speedup 1.0000x reference)
#include <cuda_runtime.h>

// cov[n] = M M^T  where M = R(q) * diag-col-scaled by s (column k scaled by s_k)
// => cov = R diag(s^2) R^T, but we compute it exactly like the reference:
//    m_ik = R_ik * s_k ; cov_ij = sum_k m_ik m_jk
//
// Memory-bound kernel: 64 B/elem traffic. Key optimization: shared-memory
// staging of the 9-float output rows so global stores are fully coalesced
// 128-bit stores instead of 9x strided STG.32 per thread.

#define TPB 256

__global__ __launch_bounds__(TPB) void cov_kernel(
    const float4* __restrict__ quat,   // [N] of (w,x,y,z)
    const float*  __restrict__ scales, // [N*3]
    float*        __restrict__ out,    // [N*9]
    int n)
{
    __shared__ float s_sc[TPB * 3];    // staged scales
    __shared__ float s_out[TPB * 9];   // staged output rows

    const int tid  = threadIdx.x;
    const int base = blockIdx.x * TPB;
    const int valid = min(TPB, n - base);

    // ---- stage scales: coalesced float4 loads (full blocks), scalar for tail ----
    if (valid == TPB) {
        const float4* s4 = reinterpret_cast<const float4*>(scales + (size_t)base * 3);
        if (tid < (TPB * 3) / 4) {
            reinterpret_cast<float4*>(s_sc)[tid] = s4[tid];
        }
    } else {
        for (int j = tid; j < valid * 3; j += TPB)
            s_sc[j] = scales[(size_t)base * 3 + j];
    }
    __syncthreads();

    // ---- compute ----
    if (tid < valid) {
        float4 q = quat[base + tid];
        float w = q.x, x = q.y, y = q.z, z = q.w;

        float xx = x * x, yy = y * y, zz = z * z;
        float xy = x * y, xz = x * z, yz = y * z;
        float wx = w * x, wy = w * y, wz = w * z;

        float r00 = 1.0f - 2.0f * (yy + zz);
        float r01 = 2.0f * (xy - wz);
        float r02 = 2.0f * (xz + wy);
        float r10 = 2.0f * (xy + wz);
        float r11 = 1.0f - 2.0f * (xx + zz);
        float r12 = 2.0f * (yz - wx);
        float r20 = 2.0f * (xz - wy);
        float r21 = 2.0f * (yz + wx);
        float r22 = 1.0f - 2.0f * (xx + yy);

        float sx = s_sc[tid * 3 + 0];
        float sy = s_sc[tid * 3 + 1];
        float sz = s_sc[tid * 3 + 2];

        // M rows
        float m00 = r00 * sx, m01 = r01 * sy, m02 = r02 * sz;
        float m10 = r10 * sx, m11 = r11 * sy, m12 = r12 * sz;
        float m20 = r20 * sx, m21 = r21 * sy, m22 = r22 * sz;

        float c00 = m00 * m00 + m01 * m01 + m02 * m02;
        float c01 = m00 * m10 + m01 * m11 + m02 * m12;
        float c02 = m00 * m20 + m01 * m21 + m02 * m22;
        float c11 = m10 * m10 + m11 * m11 + m12 * m12;
        float c12 = m10 * m20 + m11 * m21 + m12 * m22;
        float c22 = m20 * m20 + m21 * m21 + m22 * m22;

        // stride-9 STS: 9 coprime with 32 -> bank-conflict-free per column
        float* o = &s_out[tid * 9];
        o[0] = c00; o[1] = c01; o[2] = c02;
        o[3] = c01; o[4] = c11; o[5] = c12;
        o[6] = c02; o[7] = c12; o[8] = c22;
    }
    __syncthreads();

    // ---- coalesced write-out: float4 bulk + scalar tail ----
    const size_t out_base = (size_t)base * 9;
    const int nf  = valid * 9;
    const int nf4 = nf / 4;                       // # of full float4s
    float4* o4 = reinterpret_cast<float4*>(out + out_base); // 16B-aligned: base*9*4 = blockIdx*9216
    const float4* s4 = reinterpret_cast<const float4*>(s_out);
    for (int k = tid; k < nf4; k += TPB)
        o4[k] = s4[k];
    for (int k = nf4 * 4 + tid; k < nf; k += TPB)
        out[out_base + k] = s_out[k];
}

extern "C" void kernel_launch(void* const* d_in, const int* in_sizes, int n_in,
                              void* d_out, int out_size) {
    const float4* quat   = (const float4*)d_in[0]; // quaternions [N,4]
    const float*  scales = (const float*) d_in[1]; // scales [N,3]
    float* out = (float*)d_out;                    // cov [N,3,3]

    int n = in_sizes[0] / 4;
    int grid = (n + TPB - 1) / TPB;
    cov_kernel<<<grid, TPB>>>(quat, scales, out, n);
}